// round 13
// baseline (speedup 1.0000x reference)
#include <cuda_runtime.h>
#include <cuda_bf16.h>
#include <math.h>
#include <stdint.h>

// Problem constants
#define B_  2
#define L_  2048
#define D_  1024
#define H_  16
#define HD  64
#define M_  (B_ * L_)   // 4096

// ---------------------------------------------------------------------------
// Scratch (static device globals; no dynamic allocation allowed)
// ---------------------------------------------------------------------------
__device__ float g_xr[M_ * D_];              // x rounded to tf32
__device__ float g_qf[M_ * D_];              // q (tf32-rounded); reused for y
__device__ float g_kf[M_ * D_];              // k (tf32-rounded)
__device__ float g_vf[M_ * D_];              // v (tf32-rounded)
__device__ float g_wt[4 * D_ * D_];          // transposed weights, tf32-rounded
__device__ float2 g_rt[L_ * 32];             // (sin, cos) per (pos, pair)

// ---------------------------------------------------------------------------
// Helpers
// ---------------------------------------------------------------------------
__device__ __forceinline__ void mma_tf32(float* c,
                                         uint32_t a0, uint32_t a1,
                                         uint32_t a2, uint32_t a3,
                                         uint32_t b0, uint32_t b1)
{
    asm volatile(
        "mma.sync.aligned.m16n8k8.row.col.f32.tf32.tf32.f32 "
        "{%0,%1,%2,%3}, {%4,%5,%6,%7}, {%8,%9}, {%0,%1,%2,%3};"
        : "+f"(c[0]), "+f"(c[1]), "+f"(c[2]), "+f"(c[3])
        : "r"(a0), "r"(a1), "r"(a2), "r"(a3), "r"(b0), "r"(b1));
}

__device__ __forceinline__ void ldsm4(uint32_t& r0, uint32_t& r1,
                                      uint32_t& r2, uint32_t& r3, uint32_t a)
{
    asm volatile("ldmatrix.sync.aligned.m8n8.x4.shared.b16 {%0,%1,%2,%3}, [%4];"
                 : "=r"(r0), "=r"(r1), "=r"(r2), "=r"(r3) : "r"(a));
}

__device__ __forceinline__ uint32_t f2tf32(float x) {
    uint32_t u;
    asm("cvt.rna.tf32.f32 %0, %1;" : "=r"(u) : "f"(x));
    return u;
}

__device__ __forceinline__ uint32_t smem_u32(const void* p) {
    uint32_t a;
    asm("{ .reg .u64 t; cvta.to.shared.u64 t, %1; cvt.u32.u64 %0, t; }"
        : "=r"(a) : "l"(p));
    return a;
}

__device__ __forceinline__ void cpa16(uint32_t dst, const void* src) {
    asm volatile("cp.async.cg.shared.global [%0], [%1], 16;"
                 :: "r"(dst), "l"(src));
}
#define CP_COMMIT  asm volatile("cp.async.commit_group;")
#define CP_WAIT(n) asm volatile("cp.async.wait_group %0;" :: "n"(n))

// ---------------------------------------------------------------------------
// RoPE table
// ---------------------------------------------------------------------------
__global__ __launch_bounds__(256) void ropetab_kernel()
{
    int idx = blockIdx.x * blockDim.x + threadIdx.x;   // < 65536
    int pos = idx >> 5;
    int i   = idx & 31;
    float freq = exp2f(-13.287712379549449f * (float)(2 * i) * (1.0f / 64.0f));
    float s, c;
    sincosf((float)pos * freq, &s, &c);
    g_rt[idx] = make_float2(s, c);
}

// ---------------------------------------------------------------------------
// round_tf32: elementwise rna tf32 rounding (f32 -> f32)
// ---------------------------------------------------------------------------
__global__ __launch_bounds__(256) void round_tf32(
    const float* __restrict__ src, float* __restrict__ dst)
{
    int i = blockIdx.x * blockDim.x + threadIdx.x;
    float4 v = ((const float4*)src)[i];
    float4 o = make_float4(__uint_as_float(f2tf32(v.x)),
                           __uint_as_float(f2tf32(v.y)),
                           __uint_as_float(f2tf32(v.z)),
                           __uint_as_float(f2tf32(v.w)));
    ((float4*)dst)[i] = o;
}

// ---------------------------------------------------------------------------
// transpose_f32: g_wt[z][n][k] = tf32_round(W_z[k][n])
// ---------------------------------------------------------------------------
__global__ __launch_bounds__(256) void transpose_f32(
    const float* __restrict__ W0, const float* __restrict__ W1,
    const float* __restrict__ W2, const float* __restrict__ W3)
{
    __shared__ float tile[32][33];
    const float* srcs[4] = {W0, W1, W2, W3};
    const float* src = srcs[blockIdx.z];
    float* dst = g_wt + (size_t)blockIdx.z * D_ * D_;

    int x = blockIdx.x * 32 + threadIdx.x;
    int y = blockIdx.y * 32 + threadIdx.y;
#pragma unroll
    for (int i = 0; i < 4; ++i)
        tile[threadIdx.y + i * 8][threadIdx.x] = src[(size_t)(y + i * 8) * D_ + x];
    __syncthreads();
    x = blockIdx.y * 32 + threadIdx.x;
    y = blockIdx.x * 32 + threadIdx.y;
#pragma unroll
    for (int i = 0; i < 4; ++i)
        dst[(size_t)(y + i * 8) * D_ + x] =
            __uint_as_float(f2tf32(tile[threadIdx.x][threadIdx.y + i * 8]));
}

// ---------------------------------------------------------------------------
// gemm_tf32: C = alpha * A @ B^T, single-pass tf32 (m16n8k8); A,B exact tf32.
// EPI 0: QKV epilogue (Q/K: RoPE + tf32-round f32; V: tf32-round f32).
// EPI 1: plain f32 to Of32.
// ---------------------------------------------------------------------------
#define GST 36                        // smem row stride in f32 (144 B)
#define GTILE_B (128 * GST * 4)       // 18432 bytes per operand tile
#define GSTAGE_B (2 * GTILE_B)        // 36864
#define GEMM3_SMEM (2 * GSTAGE_B)     // 73728

template <int EPI>
__global__ __launch_bounds__(256, 2) void gemm_tf32(
    const float* __restrict__ A, const float* __restrict__ Bg,
    float* __restrict__ Qf, float* __restrict__ Kf,
    float* __restrict__ Vf, float* __restrict__ Of32, float alpha0)
{
    extern __shared__ char smp[];
    const uint32_t sb = smem_u32(smp);

    const int tid = threadIdx.x;
    const int wid = tid >> 5;
    const int lane = tid & 31;
    const int wm = wid & 1;
    const int wn = wid >> 1;
    const int g  = lane >> 2;
    const int t  = lane & 3;
    const int m0 = blockIdx.y * 128;
    const int nb = blockIdx.x;
    const int nrow0 = nb * 128;
    const int sel = nb >> 3;
    const int n0 = (nb & 7) * 128;

    // ldmatrix lane offsets (f32 units within a tile)
    const uint32_t aoff = (uint32_t)((lane & 15) * GST + (lane >> 4) * 4);
    const uint32_t boff = (uint32_t)(((lane & 7) + ((lane & 16) ? 8 : 0)) * GST
                                     + ((lane & 8) ? 4 : 0));

    float acc[4][4][4];
#pragma unroll
    for (int i = 0; i < 4; ++i)
#pragma unroll
        for (int j = 0; j < 4; ++j)
#pragma unroll
            for (int r = 0; r < 4; ++r) acc[i][j][r] = 0.0f;

    const int ldrow = tid >> 3;          // 0..31 (x4 -> 128 rows)
    const int ldc   = tid & 7;           // 16B chunk within 128B row

    auto issue = [&](int c, int s) {
        const int k0 = c * 32;
#pragma unroll
        for (int i = 0; i < 4; ++i) {
            int row = ldrow + i * 32;
            uint32_t so = (uint32_t)(s * GSTAGE_B + row * (GST * 4) + ldc * 16);
            cpa16(sb + so,           A  + (size_t)(m0 + row) * D_ + k0 + ldc * 4);
            cpa16(sb + so + GTILE_B, Bg + (size_t)(nrow0 + row) * D_ + k0 + ldc * 4);
        }
    };

    issue(0, 0);
    CP_COMMIT;

    for (int c = 0; c < D_ / 32; ++c) {
        const int s = c & 1;
        if (c + 1 < D_ / 32) {
            issue(c + 1, s ^ 1);
            CP_COMMIT;
            CP_WAIT(1);
        } else {
            CP_WAIT(0);
        }
        __syncthreads();

        const uint32_t Ab = sb + s * GSTAGE_B;
        const uint32_t Bb = Ab + GTILE_B;

#pragma unroll
        for (int k8 = 0; k8 < 4; ++k8) {
            uint32_t bf[4][2];
#pragma unroll
            for (int jp = 0; jp < 2; ++jp) {
                uint32_t ba = Bb + (boff + (uint32_t)((wn * 32 + jp * 16) * GST
                                                     + k8 * 8)) * 4;
                ldsm4(bf[2 * jp][0], bf[2 * jp][1],
                      bf[2 * jp + 1][0], bf[2 * jp + 1][1], ba);
            }
#pragma unroll
            for (int i = 0; i < 4; ++i) {
                uint32_t aa = Ab + (aoff + (uint32_t)((wm * 64 + i * 16) * GST
                                                     + k8 * 8)) * 4;
                uint32_t af[4];
                ldsm4(af[0], af[1], af[2], af[3], aa);
#pragma unroll
                for (int j = 0; j < 4; ++j)
                    mma_tf32(acc[i][j], af[0], af[1], af[2], af[3],
                             bf[j][0], bf[j][1]);
            }
        }
        __syncthreads();
    }

    // ---- Epilogue
    const float alpha = (EPI == 0 && sel == 0) ? alpha0 : 1.0f;
#pragma unroll
    for (int i = 0; i < 4; ++i) {
        int row = m0 + wm * 64 + i * 16 + g;
#pragma unroll
        for (int j = 0; j < 4; ++j) {
            int col = n0 + wn * 32 + j * 8 + t * 2;
            float2 o0 = make_float2(alpha * acc[i][j][0], alpha * acc[i][j][1]);
            float2 o1 = make_float2(alpha * acc[i][j][2], alpha * acc[i][j][3]);
            if (EPI == 1) {
                *(float2*)(Of32 + (size_t)row * D_ + col)       = o0;
                *(float2*)(Of32 + (size_t)(row + 8) * D_ + col) = o1;
            } else if (sel < 2) {
                // RoPE, rna-round to tf32, store f32
                int ii = (col >> 1) & 31;
                float2 sc0 = g_rt[(row & (L_ - 1)) * 32 + ii];
                float2 sc1 = g_rt[((row + 8) & (L_ - 1)) * 32 + ii];
                float r00 = o0.x * sc0.y - o0.y * sc0.x;
                float r01 = o0.y * sc0.y + o0.x * sc0.x;
                float r10 = o1.x * sc1.y - o1.y * sc1.x;
                float r11 = o1.y * sc1.y + o1.x * sc1.x;
                float* Uo = (sel == 0) ? Qf : Kf;
                *(float2*)(Uo + (size_t)row * D_ + col) =
                    make_float2(__uint_as_float(f2tf32(r00)),
                                __uint_as_float(f2tf32(r01)));
                *(float2*)(Uo + (size_t)(row + 8) * D_ + col) =
                    make_float2(__uint_as_float(f2tf32(r10)),
                                __uint_as_float(f2tf32(r11)));
            } else {
                // V: tf32-rounded f32
                *(float2*)(Vf + (size_t)row * D_ + col) =
                    make_float2(__uint_as_float(f2tf32(o0.x)),
                                __uint_as_float(f2tf32(o0.y)));
                *(float2*)(Vf + (size_t)(row + 8) * D_ + col) =
                    make_float2(__uint_as_float(f2tf32(o1.x)),
                                __uint_as_float(f2tf32(o1.y)));
            }
        }
    }
}

// ---------------------------------------------------------------------------
// flash8: all-tf32 flash attention.
// K smem rows permuted within 8-groups (pi = [0,4,1,5,2,6,3,7]) so the S
// C-fragment IS the PV tf32 A-fragment as (c0,c2,c1,c3). V natural order,
// f32 in smem; PV B-frags via conflict-free LDS.32. Double-buffered cp.async.
// y written tf32-rounded f32 (exact operand for the Wo GEMM).
// ---------------------------------------------------------------------------
#define KST 68                        // smem row stride, f32 (272 B)
#define KARR_B (64 * KST * 4)         // 17408 bytes (K tile)
#define FSTG_B (2 * KARR_B)           // 34816 (K + V)
#define FLASH_SMEM (2 * FSTG_B)       // 69632

__global__ __launch_bounds__(256, 2) void flash8(
    const float* __restrict__ qf, const float* __restrict__ kf,
    const float* __restrict__ vf, float* __restrict__ y)
{
    extern __shared__ char fsm[];
    const uint32_t sb = smem_u32(fsm);

    const int tid  = threadIdx.x;
    const int wid  = tid >> 5;
    const int lane = tid & 31;
    const int g = lane >> 2;
    const int t = lane & 3;
    const int q0 = blockIdx.x * 128;
    const int h  = blockIdx.y;
    const int b  = blockIdx.z;

    // ldmatrix lane offset for K b-frags (f32 units)
    const uint32_t koff = (uint32_t)(((lane & 7) + ((lane & 16) ? 8 : 0)) * KST
                                     + ((lane & 8) ? 4 : 0));

    // ---- Q fragments: tf32 a-frags, direct f32 loads
    uint32_t qa[8][4];
    {
        int r0 = b * L_ + q0 + wid * 16 + g;
        const uint32_t* p = (const uint32_t*)qf + (size_t)r0 * D_ + h * HD;
#pragma unroll
        for (int c = 0; c < 8; ++c) {
            qa[c][0] = p[c * 8 + t];
            qa[c][1] = p[8 * D_ + c * 8 + t];
            qa[c][2] = p[c * 8 + t + 4];
            qa[c][3] = p[8 * D_ + c * 8 + t + 4];
        }
    }

    const int ldrow = tid >> 2;     // 0..63 smem row
    const int ldch  = tid & 3;
    // permuted source key for K rows: pi within each 8-group
    const int prow = (ldrow & ~7) | ((ldrow & 1) << 2) | ((ldrow & 7) >> 1);

    auto issue_kv = [&](int tile, int s) {
        uint32_t so = sb + (uint32_t)(s * FSTG_B);
        const float* kp = kf + ((size_t)(b * L_ + tile * 64 + prow)) * D_ + h * HD;
        const float* vp = vf + ((size_t)(b * L_ + tile * 64 + ldrow)) * D_ + h * HD;
#pragma unroll
        for (int c4 = 0; c4 < 4; ++c4) {
            int ch = ldch + c4 * 4;
            cpa16(so + ldrow * (KST * 4) + ch * 16,          kp + ch * 4);
            cpa16(so + KARR_B + ldrow * (KST * 4) + ch * 16, vp + ch * 4);
        }
    };

    float acc[8][4];
#pragma unroll
    for (int j = 0; j < 8; ++j)
#pragma unroll
        for (int r = 0; r < 4; ++r) acc[j][r] = 0.0f;
    float m0r = -1e30f, m1r = -1e30f, l0r = 0.0f, l1r = 0.0f;

    issue_kv(0, 0);
    CP_COMMIT;

    for (int tile = 0; tile < L_ / 64; ++tile) {
        const int s = tile & 1;
        if (tile + 1 < L_ / 64) {
            issue_kv(tile + 1, s ^ 1);
            CP_COMMIT;
            CP_WAIT(1);
        } else {
            CP_WAIT(0);
        }
        __syncthreads();

        const uint32_t kb_ = sb + s * FSTG_B;
        const char* Vbase = fsm + s * FSTG_B + KARR_B;

        // ---- S = Q K^T, single-pass tf32 (keys permuted within 8-groups)
        float S[8][4];
#pragma unroll
        for (int j = 0; j < 8; ++j)
#pragma unroll
            for (int r = 0; r < 4; ++r) S[j][r] = 0.0f;
#pragma unroll
        for (int c = 0; c < 8; ++c) {
#pragma unroll
            for (int jp = 0; jp < 4; ++jp) {
                uint32_t a = kb_ + (koff + (uint32_t)(jp * 16 * KST + c * 8)) * 4;
                uint32_t b0a, b1a, b0b, b1b;
                ldsm4(b0a, b1a, b0b, b1b, a);
                mma_tf32(S[2 * jp],     qa[c][0], qa[c][1], qa[c][2], qa[c][3], b0a, b1a);
                mma_tf32(S[2 * jp + 1], qa[c][0], qa[c][1], qa[c][2], qa[c][3], b0b, b1b);
            }
        }

        // ---- Online softmax (permutation-invariant)
        float mx0 = -1e30f, mx1 = -1e30f;
#pragma unroll
        for (int j = 0; j < 8; ++j) {
            mx0 = fmaxf(mx0, fmaxf(S[j][0], S[j][1]));
            mx1 = fmaxf(mx1, fmaxf(S[j][2], S[j][3]));
        }
        mx0 = fmaxf(mx0, __shfl_xor_sync(0xffffffffu, mx0, 1));
        mx0 = fmaxf(mx0, __shfl_xor_sync(0xffffffffu, mx0, 2));
        mx1 = fmaxf(mx1, __shfl_xor_sync(0xffffffffu, mx1, 1));
        mx1 = fmaxf(mx1, __shfl_xor_sync(0xffffffffu, mx1, 2));

        float mn0 = fmaxf(m0r, mx0);
        float mn1 = fmaxf(m1r, mx1);
        float cr0 = __expf(m0r - mn0);
        float cr1 = __expf(m1r - mn1);
        m0r = mn0; m1r = mn1;

        float sum0 = 0.0f, sum1 = 0.0f;
#pragma unroll
        for (int j = 0; j < 8; ++j) {
            S[j][0] = __expf(S[j][0] - mn0);
            S[j][1] = __expf(S[j][1] - mn0);
            S[j][2] = __expf(S[j][2] - mn1);
            S[j][3] = __expf(S[j][3] - mn1);
            sum0 += S[j][0] + S[j][1];
            sum1 += S[j][2] + S[j][3];
        }
        sum0 += __shfl_xor_sync(0xffffffffu, sum0, 1);
        sum0 += __shfl_xor_sync(0xffffffffu, sum0, 2);
        sum1 += __shfl_xor_sync(0xffffffffu, sum1, 1);
        sum1 += __shfl_xor_sync(0xffffffffu, sum1, 2);
        l0r = l0r * cr0 + sum0;
        l1r = l1r * cr1 + sum1;
#pragma unroll
        for (int j = 0; j < 8; ++j) {
            acc[j][0] *= cr0;
            acc[j][1] *= cr0;
            acc[j][2] *= cr1;
            acc[j][3] *= cr1;
        }

        // ---- O += P V, single-pass tf32.
        // A-frag for k8 step c = (S[c][0], S[c][2], S[c][1], S[c][3]) rna->tf32
        // (valid because K rows were permuted: S col 2t = key t, 2t+1 = key t+4).
        // B-frag: V natural order, conflict-free LDS.32.
#pragma unroll
        for (int c = 0; c < 8; ++c) {
            uint32_t a0 = f2tf32(S[c][0]);
            uint32_t a1 = f2tf32(S[c][2]);
            uint32_t a2 = f2tf32(S[c][1]);
            uint32_t a3 = f2tf32(S[c][3]);
            const uint32_t* Vr0 = (const uint32_t*)(Vbase) + (8 * c + t) * KST + g;
            const uint32_t* Vr1 = Vr0 + 4 * KST;
#pragma unroll
            for (int jp = 0; jp < 8; ++jp) {
                uint32_t v0 = Vr0[jp * 8];
                uint32_t v1 = Vr1[jp * 8];
                mma_tf32(acc[jp], a0, a1, a2, a3, v0, v1);
            }
        }
        __syncthreads();
    }

    // ---- Normalize and store y (tf32-rounded f32 — exact operand for Wo)
    float inv0 = 1.0f / l0r;
    float inv1 = 1.0f / l1r;
    int row0 = b * L_ + q0 + wid * 16 + g;
    float* y0 = y + (size_t)row0 * D_ + h * HD;
    float* y1 = y0 + 8 * D_;
#pragma unroll
    for (int j = 0; j < 8; ++j) {
        *(float2*)(y0 + j * 8 + 2 * t) =
            make_float2(__uint_as_float(f2tf32(acc[j][0] * inv0)),
                        __uint_as_float(f2tf32(acc[j][1] * inv0)));
        *(float2*)(y1 + j * 8 + 2 * t) =
            make_float2(__uint_as_float(f2tf32(acc[j][2] * inv1)),
                        __uint_as_float(f2tf32(acc[j][3] * inv1)));
    }
}

// ---------------------------------------------------------------------------
// Host launcher
// ---------------------------------------------------------------------------
extern "C" void kernel_launch(void* const* d_in, const int* in_sizes, int n_in,
                              void* d_out, int out_size)
{
    const float* x  = (const float*)d_in[0];
    const float* Wq = (const float*)d_in[1];
    const float* Wk = (const float*)d_in[2];
    const float* Wv = (const float*)d_in[3];
    const float* Wo = (const float*)d_in[4];
    float* out = (float*)d_out;

    float *xr, *qf, *kf, *vf, *wt;
    cudaGetSymbolAddress((void**)&xr, g_xr);
    cudaGetSymbolAddress((void**)&qf, g_qf);
    cudaGetSymbolAddress((void**)&kf, g_kf);
    cudaGetSymbolAddress((void**)&vf, g_vf);
    cudaGetSymbolAddress((void**)&wt, g_wt);

    // 1. RoPE table, weight transpose (rna tf32), x rna-rounding
    ropetab_kernel<<<(L_ * 32) / 256, 256>>>();
    transpose_f32<<<dim3(D_ / 32, D_ / 32, 4), dim3(32, 8)>>>(Wq, Wk, Wv, Wo);
    round_tf32<<<(M_ * D_ / 4) / 256, 256>>>(x, xr);

    // 2. Fused QKV projection (single-pass tf32, all operands exact tf32)
    cudaFuncSetAttribute(gemm_tf32<0>,
                         cudaFuncAttributeMaxDynamicSharedMemorySize, GEMM3_SMEM);
    cudaFuncSetAttribute(gemm_tf32<1>,
                         cudaFuncAttributeMaxDynamicSharedMemorySize, GEMM3_SMEM);
    const float qscale = 1.0f / 32.0f;
    gemm_tf32<0><<<dim3(24, M_ / 128), 256, GEMM3_SMEM>>>(
        xr, wt, qf, kf, vf, nullptr, qscale);

    // 3. Flash attention (all tf32, permuted-K trick); y into qf
    cudaFuncSetAttribute(flash8,
                         cudaFuncAttributeMaxDynamicSharedMemorySize, FLASH_SMEM);
    dim3 fgrid(L_ / 128, H_, B_);
    flash8<<<fgrid, 256, FLASH_SMEM>>>(qf, kf, vf, qf);

    // 4. Output projection (single-pass tf32, f32 out)
    gemm_tf32<1><<<dim3(8, M_ / 128), 256, GEMM3_SMEM>>>(
        qf, wt + 3 * (size_t)D_ * D_, nullptr, nullptr, nullptr, out, 1.0f);
}

// round 17
// speedup vs baseline: 1.1520x; 1.1520x over previous
#include <cuda_runtime.h>
#include <cuda_bf16.h>
#include <math.h>
#include <stdint.h>

// Problem constants
#define B_  2
#define L_  2048
#define D_  1024
#define H_  16
#define HD  64
#define M_  (B_ * L_)   // 4096

// ---------------------------------------------------------------------------
// Scratch (static device globals; no dynamic allocation allowed)
// ---------------------------------------------------------------------------
__device__ float g_xr[M_ * D_];              // x rounded to tf32
__device__ float g_qf[M_ * D_];              // q (tf32-rounded); reused for y
__device__ float g_kf[M_ * D_];              // k (tf32-rounded)
__device__ float g_vt[M_ * D_];              // V^T: [(b*1024 + d)][token], tf32
__device__ float g_wt[4 * D_ * D_];          // transposed weights, tf32-rounded
__device__ float2 g_rt[L_ * 32];             // (sin, cos) per (pos, pair)

// ---------------------------------------------------------------------------
// Helpers
// ---------------------------------------------------------------------------
__device__ __forceinline__ void mma_tf32(float* c,
                                         uint32_t a0, uint32_t a1,
                                         uint32_t a2, uint32_t a3,
                                         uint32_t b0, uint32_t b1)
{
    asm volatile(
        "mma.sync.aligned.m16n8k8.row.col.f32.tf32.tf32.f32 "
        "{%0,%1,%2,%3}, {%4,%5,%6,%7}, {%8,%9}, {%0,%1,%2,%3};"
        : "+f"(c[0]), "+f"(c[1]), "+f"(c[2]), "+f"(c[3])
        : "r"(a0), "r"(a1), "r"(a2), "r"(a3), "r"(b0), "r"(b1));
}

__device__ __forceinline__ void ldsm4(uint32_t& r0, uint32_t& r1,
                                      uint32_t& r2, uint32_t& r3, uint32_t a)
{
    asm volatile("ldmatrix.sync.aligned.m8n8.x4.shared.b16 {%0,%1,%2,%3}, [%4];"
                 : "=r"(r0), "=r"(r1), "=r"(r2), "=r"(r3) : "r"(a));
}

__device__ __forceinline__ uint32_t f2tf32(float x) {
    uint32_t u;
    asm("cvt.rna.tf32.f32 %0, %1;" : "=r"(u) : "f"(x));
    return u;
}

__device__ __forceinline__ uint32_t smem_u32(const void* p) {
    uint32_t a;
    asm("{ .reg .u64 t; cvta.to.shared.u64 t, %1; cvt.u32.u64 %0, t; }"
        : "=r"(a) : "l"(p));
    return a;
}

__device__ __forceinline__ void cpa16(uint32_t dst, const void* src) {
    asm volatile("cp.async.cg.shared.global [%0], [%1], 16;"
                 :: "r"(dst), "l"(src));
}
#define CP_COMMIT  asm volatile("cp.async.commit_group;")
#define CP_WAIT(n) asm volatile("cp.async.wait_group %0;" :: "n"(n))

// ---------------------------------------------------------------------------
// RoPE table
// ---------------------------------------------------------------------------
__global__ __launch_bounds__(256) void ropetab_kernel()
{
    int idx = blockIdx.x * blockDim.x + threadIdx.x;   // < 65536
    int pos = idx >> 5;
    int i   = idx & 31;
    float freq = exp2f(-13.287712379549449f * (float)(2 * i) * (1.0f / 64.0f));
    float s, c;
    sincosf((float)pos * freq, &s, &c);
    g_rt[idx] = make_float2(s, c);
}

// ---------------------------------------------------------------------------
// round_tf32: elementwise rna tf32 rounding (f32 -> f32)
// ---------------------------------------------------------------------------
__global__ __launch_bounds__(256) void round_tf32(
    const float* __restrict__ src, float* __restrict__ dst)
{
    int i = blockIdx.x * blockDim.x + threadIdx.x;
    float4 v = ((const float4*)src)[i];
    float4 o = make_float4(__uint_as_float(f2tf32(v.x)),
                           __uint_as_float(f2tf32(v.y)),
                           __uint_as_float(f2tf32(v.z)),
                           __uint_as_float(f2tf32(v.w)));
    ((float4*)dst)[i] = o;
}

// ---------------------------------------------------------------------------
// transpose_f32: g_wt[z][n][k] = tf32_round(W_z[k][n])
// ---------------------------------------------------------------------------
__global__ __launch_bounds__(256) void transpose_f32(
    const float* __restrict__ W0, const float* __restrict__ W1,
    const float* __restrict__ W2, const float* __restrict__ W3)
{
    __shared__ float tile[32][33];
    const float* srcs[4] = {W0, W1, W2, W3};
    const float* src = srcs[blockIdx.z];
    float* dst = g_wt + (size_t)blockIdx.z * D_ * D_;

    int x = blockIdx.x * 32 + threadIdx.x;
    int y = blockIdx.y * 32 + threadIdx.y;
#pragma unroll
    for (int i = 0; i < 4; ++i)
        tile[threadIdx.y + i * 8][threadIdx.x] = src[(size_t)(y + i * 8) * D_ + x];
    __syncthreads();
    x = blockIdx.y * 32 + threadIdx.x;
    y = blockIdx.x * 32 + threadIdx.y;
#pragma unroll
    for (int i = 0; i < 4; ++i)
        dst[(size_t)(y + i * 8) * D_ + x] =
            __uint_as_float(f2tf32(tile[threadIdx.x][threadIdx.y + i * 8]));
}

// ---------------------------------------------------------------------------
// gemm_tf32: C = alpha * A @ B^T, single-pass tf32 (m16n8k8); A,B exact tf32.
// EPI 0: QKV epilogue (Q/K: RoPE + tf32-round f32; V: transposed tf32 f32
//        into Vt[(b*1024 + d)][token]).
// EPI 1: plain f32 to Of32.
// CTA 128x128, K-chunk 32, 2-stage cp.async, ldmatrix-on-f32 fragments.
// ---------------------------------------------------------------------------
#define GST 36                        // smem row stride in f32 (144 B)
#define GTILE_B (128 * GST * 4)       // 18432 bytes per operand tile
#define GSTAGE_B (2 * GTILE_B)        // 36864
#define GEMM3_SMEM (2 * GSTAGE_B)     // 73728

template <int EPI>
__global__ __launch_bounds__(256, 2) void gemm_tf32(
    const float* __restrict__ A, const float* __restrict__ Bg,
    float* __restrict__ Qf, float* __restrict__ Kf,
    float* __restrict__ Vt, float* __restrict__ Of32, float alpha0)
{
    extern __shared__ char smp[];
    const uint32_t sb = smem_u32(smp);

    const int tid = threadIdx.x;
    const int wid = tid >> 5;
    const int lane = tid & 31;
    const int wm = wid & 1;
    const int wn = wid >> 1;
    const int g  = lane >> 2;
    const int t  = lane & 3;
    const int m0 = blockIdx.y * 128;
    const int nb = blockIdx.x;
    const int nrow0 = nb * 128;
    const int sel = nb >> 3;
    const int n0 = (nb & 7) * 128;

    // ldmatrix lane offsets (f32 units within a tile)
    const uint32_t aoff = (uint32_t)((lane & 15) * GST + (lane >> 4) * 4);
    const uint32_t boff = (uint32_t)(((lane & 7) + ((lane & 16) ? 8 : 0)) * GST
                                     + ((lane & 8) ? 4 : 0));

    float acc[4][4][4];
#pragma unroll
    for (int i = 0; i < 4; ++i)
#pragma unroll
        for (int j = 0; j < 4; ++j)
#pragma unroll
            for (int r = 0; r < 4; ++r) acc[i][j][r] = 0.0f;

    const int ldrow = tid >> 3;          // 0..31 (x4 -> 128 rows)
    const int ldc   = tid & 7;           // 16B chunk within 128B row

    auto issue = [&](int c, int s) {
        const int k0 = c * 32;
#pragma unroll
        for (int i = 0; i < 4; ++i) {
            int row = ldrow + i * 32;
            uint32_t so = (uint32_t)(s * GSTAGE_B + row * (GST * 4) + ldc * 16);
            cpa16(sb + so,           A  + (size_t)(m0 + row) * D_ + k0 + ldc * 4);
            cpa16(sb + so + GTILE_B, Bg + (size_t)(nrow0 + row) * D_ + k0 + ldc * 4);
        }
    };

    issue(0, 0);
    CP_COMMIT;

    for (int c = 0; c < D_ / 32; ++c) {
        const int s = c & 1;
        if (c + 1 < D_ / 32) {
            issue(c + 1, s ^ 1);
            CP_COMMIT;
            CP_WAIT(1);
        } else {
            CP_WAIT(0);
        }
        __syncthreads();

        const uint32_t Ab = sb + s * GSTAGE_B;
        const uint32_t Bb = Ab + GTILE_B;

#pragma unroll
        for (int k8 = 0; k8 < 4; ++k8) {
            uint32_t bf[4][2];
#pragma unroll
            for (int jp = 0; jp < 2; ++jp) {
                uint32_t ba = Bb + (boff + (uint32_t)((wn * 32 + jp * 16) * GST
                                                     + k8 * 8)) * 4;
                ldsm4(bf[2 * jp][0], bf[2 * jp][1],
                      bf[2 * jp + 1][0], bf[2 * jp + 1][1], ba);
            }
#pragma unroll
            for (int i = 0; i < 4; ++i) {
                uint32_t aa = Ab + (aoff + (uint32_t)((wm * 64 + i * 16) * GST
                                                     + k8 * 8)) * 4;
                uint32_t af[4];
                ldsm4(af[0], af[1], af[2], af[3], aa);
#pragma unroll
                for (int j = 0; j < 4; ++j)
                    mma_tf32(acc[i][j], af[0], af[1], af[2], af[3],
                             bf[j][0], bf[j][1]);
            }
        }
        __syncthreads();
    }

    // ---- Epilogue
    const float alpha = (EPI == 0 && sel == 0) ? alpha0 : 1.0f;
#pragma unroll
    for (int i = 0; i < 4; ++i) {
        int row = m0 + wm * 64 + i * 16 + g;
#pragma unroll
        for (int j = 0; j < 4; ++j) {
            int col = n0 + wn * 32 + j * 8 + t * 2;
            float2 o0 = make_float2(alpha * acc[i][j][0], alpha * acc[i][j][1]);
            float2 o1 = make_float2(alpha * acc[i][j][2], alpha * acc[i][j][3]);
            if (EPI == 1) {
                *(float2*)(Of32 + (size_t)row * D_ + col)       = o0;
                *(float2*)(Of32 + (size_t)(row + 8) * D_ + col) = o1;
            } else if (sel < 2) {
                // RoPE, rna-round to tf32, store f32
                int ii = (col >> 1) & 31;
                float2 sc0 = g_rt[(row & (L_ - 1)) * 32 + ii];
                float2 sc1 = g_rt[((row + 8) & (L_ - 1)) * 32 + ii];
                float r00 = o0.x * sc0.y - o0.y * sc0.x;
                float r01 = o0.y * sc0.y + o0.x * sc0.x;
                float r10 = o1.x * sc1.y - o1.y * sc1.x;
                float r11 = o1.y * sc1.y + o1.x * sc1.x;
                float* Uo = (sel == 0) ? Qf : Kf;
                *(float2*)(Uo + (size_t)row * D_ + col) =
                    make_float2(__uint_as_float(f2tf32(r00)),
                                __uint_as_float(f2tf32(r01)));
                *(float2*)(Uo + (size_t)(row + 8) * D_ + col) =
                    make_float2(__uint_as_float(f2tf32(r10)),
                                __uint_as_float(f2tf32(r11)));
            } else {
                // V: transposed store, tf32-rounded f32.
                // Vt[(b*1024 + d) * L_ + token]
                int bb0 = row >> 11;
                int tk0 = row & (L_ - 1);
                int bb1 = (row + 8) >> 11;
                int tk1 = (row + 8) & (L_ - 1);
                Vt[((size_t)(bb0 * D_ + col))     * L_ + tk0] = __uint_as_float(f2tf32(o0.x));
                Vt[((size_t)(bb0 * D_ + col + 1)) * L_ + tk0] = __uint_as_float(f2tf32(o0.y));
                Vt[((size_t)(bb1 * D_ + col))     * L_ + tk1] = __uint_as_float(f2tf32(o1.x));
                Vt[((size_t)(bb1 * D_ + col + 1)) * L_ + tk1] = __uint_as_float(f2tf32(o1.y));
            }
        }
    }
}

// ---------------------------------------------------------------------------
// flash10: all-tf32 flash attention (R13 numerics, fixed V path).
// K smem rows permuted within 8-groups (pi = [0,4,1,5,2,6,3,7]) so the S
// C-fragment IS the PV tf32 A-fragment as (c0,c2,c1,c3). V pre-transposed in
// gmem; V^T tile loaded coalesced, PV B-frags via the proven ldsm4-on-f32
// pattern (conflict-free). Double-buffered cp.async.
// y written tf32-rounded f32 (exact operand for the Wo GEMM).
// ---------------------------------------------------------------------------
#define KST 68                        // smem row stride, f32 (272 B)
#define KARR_B (64 * KST * 4)         // 17408 bytes (K tile)
#define FSTG_B (2 * KARR_B)           // 34816 (K + V^T)
#define FLASH_SMEM (2 * FSTG_B)       // 69632

__global__ __launch_bounds__(256, 2) void flash10(
    const float* __restrict__ qf, const float* __restrict__ kf,
    const float* __restrict__ vt, float* __restrict__ y)
{
    extern __shared__ char fsm[];
    const uint32_t sb = smem_u32(fsm);

    const int tid  = threadIdx.x;
    const int wid  = tid >> 5;
    const int lane = tid & 31;
    const int g = lane >> 2;
    const int t = lane & 3;
    const int q0 = blockIdx.x * 128;
    const int h  = blockIdx.y;
    const int b  = blockIdx.z;

    // ldmatrix lane offsets (f32 units): same b-frag recipe as the GEMM
    const uint32_t koff = (uint32_t)(((lane & 7) + ((lane & 16) ? 8 : 0)) * KST
                                     + ((lane & 8) ? 4 : 0));
    const uint32_t voff = koff;   // identical pattern, V^T tile has same stride

    // ---- Q fragments: tf32 a-frags, direct f32 loads
    uint32_t qa[8][4];
    {
        int r0 = b * L_ + q0 + wid * 16 + g;
        const uint32_t* p = (const uint32_t*)qf + (size_t)r0 * D_ + h * HD;
#pragma unroll
        for (int c = 0; c < 8; ++c) {
            qa[c][0] = p[c * 8 + t];
            qa[c][1] = p[8 * D_ + c * 8 + t];
            qa[c][2] = p[c * 8 + t + 4];
            qa[c][3] = p[8 * D_ + c * 8 + t + 4];
        }
    }

    const int ldrow = tid >> 2;     // 0..63 smem row
    const int ldch  = tid & 3;
    // permuted source key for K rows: pi = [0,4,1,5,2,6,3,7] within 8-groups
    const int prow = (ldrow & ~7) | ((ldrow & 1) << 2) | ((ldrow & 7) >> 1);

    auto issue_kv = [&](int tile, int s) {
        uint32_t so = sb + (uint32_t)(s * FSTG_B);
        const float* kp = kf + ((size_t)(b * L_ + tile * 64 + prow)) * D_ + h * HD;
        // V^T row d = ldrow for this head; 64 tokens starting at tile*64
        const float* vp = vt + ((size_t)(b * D_ + h * HD + ldrow)) * L_ + tile * 64;
#pragma unroll
        for (int c4 = 0; c4 < 4; ++c4) {
            int ch = ldch + c4 * 4;
            cpa16(so + ldrow * (KST * 4) + ch * 16,          kp + ch * 4);
            cpa16(so + KARR_B + ldrow * (KST * 4) + ch * 16, vp + ch * 4);
        }
    };

    float acc[8][4];
#pragma unroll
    for (int j = 0; j < 8; ++j)
#pragma unroll
        for (int r = 0; r < 4; ++r) acc[j][r] = 0.0f;
    float m0r = -1e30f, m1r = -1e30f, l0r = 0.0f, l1r = 0.0f;

    issue_kv(0, 0);
    CP_COMMIT;

    for (int tile = 0; tile < L_ / 64; ++tile) {
        const int s = tile & 1;
        if (tile + 1 < L_ / 64) {
            issue_kv(tile + 1, s ^ 1);
            CP_COMMIT;
            CP_WAIT(1);
        } else {
            CP_WAIT(0);
        }
        __syncthreads();

        const uint32_t kb_ = sb + s * FSTG_B;
        const uint32_t vb_ = kb_ + KARR_B;

        // ---- S = Q K^T, single-pass tf32 (keys permuted within 8-groups)
        float S[8][4];
#pragma unroll
        for (int j = 0; j < 8; ++j)
#pragma unroll
            for (int r = 0; r < 4; ++r) S[j][r] = 0.0f;
#pragma unroll
        for (int c = 0; c < 8; ++c) {
#pragma unroll
            for (int jp = 0; jp < 4; ++jp) {
                uint32_t a = kb_ + (koff + (uint32_t)(jp * 16 * KST + c * 8)) * 4;
                uint32_t b0a, b1a, b0b, b1b;
                ldsm4(b0a, b1a, b0b, b1b, a);
                mma_tf32(S[2 * jp],     qa[c][0], qa[c][1], qa[c][2], qa[c][3], b0a, b1a);
                mma_tf32(S[2 * jp + 1], qa[c][0], qa[c][1], qa[c][2], qa[c][3], b0b, b1b);
            }
        }

        // ---- Online softmax (permutation-invariant)
        float mx0 = -1e30f, mx1 = -1e30f;
#pragma unroll
        for (int j = 0; j < 8; ++j) {
            mx0 = fmaxf(mx0, fmaxf(S[j][0], S[j][1]));
            mx1 = fmaxf(mx1, fmaxf(S[j][2], S[j][3]));
        }
        mx0 = fmaxf(mx0, __shfl_xor_sync(0xffffffffu, mx0, 1));
        mx0 = fmaxf(mx0, __shfl_xor_sync(0xffffffffu, mx0, 2));
        mx1 = fmaxf(mx1, __shfl_xor_sync(0xffffffffu, mx1, 1));
        mx1 = fmaxf(mx1, __shfl_xor_sync(0xffffffffu, mx1, 2));

        float mn0 = fmaxf(m0r, mx0);
        float mn1 = fmaxf(m1r, mx1);
        float cr0 = __expf(m0r - mn0);
        float cr1 = __expf(m1r - mn1);
        m0r = mn0; m1r = mn1;

        float sum0 = 0.0f, sum1 = 0.0f;
#pragma unroll
        for (int j = 0; j < 8; ++j) {
            S[j][0] = __expf(S[j][0] - mn0);
            S[j][1] = __expf(S[j][1] - mn0);
            S[j][2] = __expf(S[j][2] - mn1);
            S[j][3] = __expf(S[j][3] - mn1);
            sum0 += S[j][0] + S[j][1];
            sum1 += S[j][2] + S[j][3];
        }
        sum0 += __shfl_xor_sync(0xffffffffu, sum0, 1);
        sum0 += __shfl_xor_sync(0xffffffffu, sum0, 2);
        sum1 += __shfl_xor_sync(0xffffffffu, sum1, 1);
        sum1 += __shfl_xor_sync(0xffffffffu, sum1, 2);
        l0r = l0r * cr0 + sum0;
        l1r = l1r * cr1 + sum1;
#pragma unroll
        for (int j = 0; j < 8; ++j) {
            acc[j][0] *= cr0;
            acc[j][1] *= cr0;
            acc[j][2] *= cr1;
            acc[j][3] *= cr1;
        }

        // ---- O += P V, single-pass tf32.
        // A-frag for k8 step c = (S[c][0], S[c][2], S[c][1], S[c][3]) rna->tf32
        // (valid: K rows permuted so S col 2t = key t, 2t+1 = key t+4).
        // B-frag: ldsm4 on V^T tile, same recipe as GEMM B (conflict-free).
#pragma unroll
        for (int c = 0; c < 8; ++c) {
            uint32_t a0 = f2tf32(S[c][0]);
            uint32_t a1 = f2tf32(S[c][2]);
            uint32_t a2 = f2tf32(S[c][1]);
            uint32_t a3 = f2tf32(S[c][3]);
#pragma unroll
            for (int jp = 0; jp < 4; ++jp) {
                uint32_t a = vb_ + (voff + (uint32_t)(jp * 16 * KST + c * 8)) * 4;
                uint32_t b0a, b1a, b0b, b1b;
                ldsm4(b0a, b1a, b0b, b1b, a);
                mma_tf32(acc[2 * jp],     a0, a1, a2, a3, b0a, b1a);
                mma_tf32(acc[2 * jp + 1], a0, a1, a2, a3, b0b, b1b);
            }
        }
        __syncthreads();
    }

    // ---- Normalize and store y (tf32-rounded f32 — exact operand for Wo)
    float inv0 = 1.0f / l0r;
    float inv1 = 1.0f / l1r;
    int row0 = b * L_ + q0 + wid * 16 + g;
    float* y0 = y + (size_t)row0 * D_ + h * HD;
    float* y1 = y0 + 8 * D_;
#pragma unroll
    for (int j = 0; j < 8; ++j) {
        *(float2*)(y0 + j * 8 + 2 * t) =
            make_float2(__uint_as_float(f2tf32(acc[j][0] * inv0)),
                        __uint_as_float(f2tf32(acc[j][1] * inv0)));
        *(float2*)(y1 + j * 8 + 2 * t) =
            make_float2(__uint_as_float(f2tf32(acc[j][2] * inv1)),
                        __uint_as_float(f2tf32(acc[j][3] * inv1)));
    }
}

// ---------------------------------------------------------------------------
// Host launcher
// ---------------------------------------------------------------------------
extern "C" void kernel_launch(void* const* d_in, const int* in_sizes, int n_in,
                              void* d_out, int out_size)
{
    const float* x  = (const float*)d_in[0];
    const float* Wq = (const float*)d_in[1];
    const float* Wk = (const float*)d_in[2];
    const float* Wv = (const float*)d_in[3];
    const float* Wo = (const float*)d_in[4];
    float* out = (float*)d_out;

    float *xr, *qf, *kf, *vt, *wt;
    cudaGetSymbolAddress((void**)&xr, g_xr);
    cudaGetSymbolAddress((void**)&qf, g_qf);
    cudaGetSymbolAddress((void**)&kf, g_kf);
    cudaGetSymbolAddress((void**)&vt, g_vt);
    cudaGetSymbolAddress((void**)&wt, g_wt);

    // 1. RoPE table, weight transpose (rna tf32), x rna-rounding
    ropetab_kernel<<<(L_ * 32) / 256, 256>>>();
    transpose_f32<<<dim3(D_ / 32, D_ / 32, 4), dim3(32, 8)>>>(Wq, Wk, Wv, Wo);
    round_tf32<<<(M_ * D_ / 4) / 256, 256>>>(x, xr);

    // 2. Fused QKV projection (single-pass tf32; V written transposed)
    cudaFuncSetAttribute(gemm_tf32<0>,
                         cudaFuncAttributeMaxDynamicSharedMemorySize, GEMM3_SMEM);
    cudaFuncSetAttribute(gemm_tf32<1>,
                         cudaFuncAttributeMaxDynamicSharedMemorySize, GEMM3_SMEM);
    const float qscale = 1.0f / 32.0f;
    gemm_tf32<0><<<dim3(24, M_ / 128), 256, GEMM3_SMEM>>>(
        xr, wt, qf, kf, vt, nullptr, qscale);

    // 3. Flash attention (all tf32, permuted-K + V^T ldsm path); y into qf
    cudaFuncSetAttribute(flash10,
                         cudaFuncAttributeMaxDynamicSharedMemorySize, FLASH_SMEM);
    dim3 fgrid(L_ / 128, H_, B_);
    flash10<<<fgrid, 256, FLASH_SMEM>>>(qf, kf, vt, qf);

    // 4. Output projection (single-pass tf32, f32 out)
    gemm_tf32<1><<<dim3(8, M_ / 128), 256, GEMM3_SMEM>>>(
        qf, wt + 3 * (size_t)D_ * D_, nullptr, nullptr, nullptr, out, 1.0f);
}